// round 1
// baseline (speedup 1.0000x reference)
#include <cuda_runtime.h>

#define N_ACT 300000
#define C 128
#define NTAPS 8   /* off-center taps */
#define EPSV 1e-4f

// ---------------- scratch (device globals; no allocation allowed) ----------
__device__ float g_buf1[N_ACT * C];   // conv output accumulator
__device__ float g_buf2[N_ACT * C];   // bn/relu intermediate
__device__ int   g_pin [NTAPS * N_ACT];
__device__ int   g_pout[NTAPS * N_ACT];
__device__ int   g_cnt [NTAPS];
__device__ float g_sum[C], g_sq[C];
__device__ float g_scale[C], g_shift[C];

// ---------------- utility kernels ------------------------------------------
__global__ void zero_all_k() {
    int t = threadIdx.x;
    if (t < NTAPS) g_cnt[t] = 0;
    if (t < C) { g_sum[t] = 0.f; g_sq[t] = 0.f; }
}
__global__ void zero_sums_k() {
    int t = threadIdx.x;
    if (t < C) { g_sum[t] = 0.f; g_sq[t] = 0.f; }
}

// Build compacted (in,out) pair lists for the 8 off-center taps.
__global__ void rulebook_k(const int* __restrict__ nbr) {
    int i = blockIdx.x * blockDim.x + threadIdx.x;
    if (i >= N_ACT) return;
#pragma unroll
    for (int k = 0; k < 9; k++) {
        if (k == 4) continue;
        int idx = nbr[i * 9 + k];
        if (idx >= 0) {
            int t = (k < 4) ? k : k - 1;
            int p = atomicAdd(&g_cnt[t], 1);
            g_pin [t * N_ACT + p] = idx;
            g_pout[t * N_ACT + p] = i;
        }
    }
}

// ---------------- dense center-tap GEMM: out = gather(in, nbr[:,4]) @ Wk ----
// Tile: 64 rows x 128 cols, BK=32, 256 threads, 4x8 micro-tile per thread.
__global__ __launch_bounds__(256) void gemm_center_k(
    const float* __restrict__ in, const int* __restrict__ nbr,
    const float* __restrict__ Wk, float* __restrict__ out)
{
    __shared__ float Xs[32][68];     // transposed: Xs[kd][m]
    __shared__ float Ws[32][128];    // Ws[kd][n]
    __shared__ int   rowidx[64];

    int tid = threadIdx.x;
    int m0  = blockIdx.x * 64;
    int tx  = tid & 15;      // n-group (8 cols)
    int ty  = tid >> 4;      // m-group (4 rows)

    if (tid < 64) {
        int m = m0 + tid;
        rowidx[tid] = (m < N_ACT) ? nbr[m * 9 + 4] : -1;
    }
    __syncthreads();

    float acc[4][8];
#pragma unroll
    for (int i = 0; i < 4; i++)
#pragma unroll
        for (int j = 0; j < 8; j++) acc[i][j] = 0.f;

    for (int kk = 0; kk < C; kk += 32) {
#pragma unroll
        for (int l = 0; l < 2; l++) {
            int slot = tid + l * 256;       // 0..511
            int r = slot >> 3, c4 = slot & 7;
            int row = rowidx[r];
            float4 v = make_float4(0.f, 0.f, 0.f, 0.f);
            if (row >= 0) v = *(const float4*)&in[row * C + kk + c4 * 4];
            Xs[c4 * 4 + 0][r] = v.x; Xs[c4 * 4 + 1][r] = v.y;
            Xs[c4 * 4 + 2][r] = v.z; Xs[c4 * 4 + 3][r] = v.w;
        }
#pragma unroll
        for (int l = 0; l < 4; l++) {
            int slot = tid + l * 256;       // 0..1023
            int r = slot >> 5, c4 = slot & 31;
            *(float4*)&Ws[r][c4 * 4] = *(const float4*)&Wk[(kk + r) * C + c4 * 4];
        }
        __syncthreads();
#pragma unroll
        for (int kd = 0; kd < 32; kd++) {
            float4 a  = *(float4*)&Xs[kd][ty * 4];
            float4 b0 = *(float4*)&Ws[kd][tx * 8];
            float4 b1 = *(float4*)&Ws[kd][tx * 8 + 4];
            float av[4] = {a.x, a.y, a.z, a.w};
            float bv[8] = {b0.x, b0.y, b0.z, b0.w, b1.x, b1.y, b1.z, b1.w};
#pragma unroll
            for (int i = 0; i < 4; i++)
#pragma unroll
                for (int j = 0; j < 8; j++) acc[i][j] += av[i] * bv[j];
        }
        __syncthreads();
    }
#pragma unroll
    for (int i = 0; i < 4; i++) {
        int m = m0 + ty * 4 + i;
        if (m < N_ACT) {
            *(float4*)&out[m * C + tx * 8]     = make_float4(acc[i][0], acc[i][1], acc[i][2], acc[i][3]);
            *(float4*)&out[m * C + tx * 8 + 4] = make_float4(acc[i][4], acc[i][5], acc[i][6], acc[i][7]);
        }
    }
}

// ---------------- sparse tap gather-GEMM-scatter (accumulates into out) ----
__global__ __launch_bounds__(256) void gemm_scatter_k(
    const float* __restrict__ in, const float* __restrict__ W,
    float* __restrict__ out)
{
    int t = blockIdx.y;
    int cnt = g_cnt[t];
    int m0 = blockIdx.x * 64;
    if (m0 >= cnt) return;
    int k = (t < 4) ? t : t + 1;
    const float* Wk = W + k * C * C;

    __shared__ float Xs[32][68];
    __shared__ float Ws[32][128];
    __shared__ int   rin[64], rout[64];

    int tid = threadIdx.x;
    int tx = tid & 15, ty = tid >> 4;

    if (tid < 64) {
        int m = m0 + tid;
        if (m < cnt) { rin[tid] = g_pin[t * N_ACT + m]; rout[tid] = g_pout[t * N_ACT + m]; }
        else         { rin[tid] = -1;                   rout[tid] = -1; }
    }
    __syncthreads();

    float acc[4][8];
#pragma unroll
    for (int i = 0; i < 4; i++)
#pragma unroll
        for (int j = 0; j < 8; j++) acc[i][j] = 0.f;

    for (int kk = 0; kk < C; kk += 32) {
#pragma unroll
        for (int l = 0; l < 2; l++) {
            int slot = tid + l * 256;
            int r = slot >> 3, c4 = slot & 7;
            int row = rin[r];
            float4 v = make_float4(0.f, 0.f, 0.f, 0.f);
            if (row >= 0) v = *(const float4*)&in[row * C + kk + c4 * 4];
            Xs[c4 * 4 + 0][r] = v.x; Xs[c4 * 4 + 1][r] = v.y;
            Xs[c4 * 4 + 2][r] = v.z; Xs[c4 * 4 + 3][r] = v.w;
        }
#pragma unroll
        for (int l = 0; l < 4; l++) {
            int slot = tid + l * 256;
            int r = slot >> 5, c4 = slot & 31;
            *(float4*)&Ws[r][c4 * 4] = *(const float4*)&Wk[(kk + r) * C + c4 * 4];
        }
        __syncthreads();
#pragma unroll
        for (int kd = 0; kd < 32; kd++) {
            float4 a  = *(float4*)&Xs[kd][ty * 4];
            float4 b0 = *(float4*)&Ws[kd][tx * 8];
            float4 b1 = *(float4*)&Ws[kd][tx * 8 + 4];
            float av[4] = {a.x, a.y, a.z, a.w};
            float bv[8] = {b0.x, b0.y, b0.z, b0.w, b1.x, b1.y, b1.z, b1.w};
#pragma unroll
            for (int i = 0; i < 4; i++)
#pragma unroll
                for (int j = 0; j < 8; j++) acc[i][j] += av[i] * bv[j];
        }
        __syncthreads();
    }
#pragma unroll
    for (int i = 0; i < 4; i++) {
        int ro = rout[ty * 4 + i];
        if (ro >= 0) {
#pragma unroll
            for (int j = 0; j < 8; j++)
                atomicAdd(&out[ro * C + tx * 8 + j], acc[i][j]);
        }
    }
}

// ---------------- per-channel sum / sum-of-squares --------------------------
__global__ __launch_bounds__(256) void stats_k(const float* __restrict__ y) {
    int c4 = threadIdx.x & 31;                        // float4 channel group
    int rbase = blockIdx.x * 256 + (threadIdx.x >> 5);
    float4 s = make_float4(0.f, 0.f, 0.f, 0.f);
    float4 q = make_float4(0.f, 0.f, 0.f, 0.f);
#pragma unroll 4
    for (int it = 0; it < 32; it++) {
        int r = rbase + it * 8;
        if (r < N_ACT) {
            float4 v = *(const float4*)&y[r * C + c4 * 4];
            s.x += v.x; s.y += v.y; s.z += v.z; s.w += v.w;
            q.x += v.x * v.x; q.y += v.y * v.y; q.z += v.z * v.z; q.w += v.w * v.w;
        }
    }
    int c = c4 * 4;
    atomicAdd(&g_sum[c + 0], s.x); atomicAdd(&g_sum[c + 1], s.y);
    atomicAdd(&g_sum[c + 2], s.z); atomicAdd(&g_sum[c + 3], s.w);
    atomicAdd(&g_sq [c + 0], q.x); atomicAdd(&g_sq [c + 1], q.y);
    atomicAdd(&g_sq [c + 2], q.z); atomicAdd(&g_sq [c + 3], q.w);
}

__global__ void finalize_k(const float* __restrict__ gamma, const float* __restrict__ beta) {
    int c = threadIdx.x;
    float mean = g_sum[c] * (1.f / N_ACT);
    float var  = g_sq[c] * (1.f / N_ACT) - mean * mean;
    float istd = rsqrtf(var + EPSV);
    float sc = gamma[c] * istd;
    g_scale[c] = sc;
    g_shift[c] = beta[c] - mean * sc;
}

// ---------------- elementwise: bn + relu ------------------------------------
__global__ __launch_bounds__(256) void bnrelu_k(const float* __restrict__ in, float* __restrict__ outp) {
    int i = blockIdx.x * blockDim.x + threadIdx.x;     // float4 index
    if (i >= N_ACT * C / 4) return;
    int c4 = (i & 31) * 4;
    float4 v  = ((const float4*)in)[i];
    float4 sc = *(const float4*)&g_scale[c4];
    float4 sh = *(const float4*)&g_shift[c4];
    float4 o;
    o.x = fmaxf(v.x * sc.x + sh.x, 0.f);
    o.y = fmaxf(v.y * sc.y + sh.y, 0.f);
    o.z = fmaxf(v.z * sc.z + sh.z, 0.f);
    o.w = fmaxf(v.w * sc.w + sh.w, 0.f);
    ((float4*)outp)[i] = o;
}

// ---------------- elementwise: bn + residual + relu -> d_out ----------------
__global__ __launch_bounds__(256) void final_k(
    const float* __restrict__ y, const float* __restrict__ x, float* __restrict__ outp)
{
    int i = blockIdx.x * blockDim.x + threadIdx.x;
    if (i >= N_ACT * C / 4) return;
    int c4 = (i & 31) * 4;
    float4 v  = ((const float4*)y)[i];
    float4 xv = ((const float4*)x)[i];
    float4 sc = *(const float4*)&g_scale[c4];
    float4 sh = *(const float4*)&g_shift[c4];
    float4 o;
    o.x = fmaxf(v.x * sc.x + sh.x + xv.x, 0.f);
    o.y = fmaxf(v.y * sc.y + sh.y + xv.y, 0.f);
    o.z = fmaxf(v.z * sc.z + sh.z + xv.z, 0.f);
    o.w = fmaxf(v.w * sc.w + sh.w + xv.w, 0.f);
    ((float4*)outp)[i] = o;
}

// ---------------- launch -----------------------------------------------------
extern "C" void kernel_launch(void* const* d_in, const int* in_sizes, int n_in,
                              void* d_out, int out_size)
{
    const float* x   = (const float*)d_in[0];
    const int*   nbr = (const int*)  d_in[1];
    const float* W1  = (const float*)d_in[2];
    const float* g1  = (const float*)d_in[3];
    const float* b1  = (const float*)d_in[4];
    const float* W2  = (const float*)d_in[5];
    const float* g2  = (const float*)d_in[6];
    const float* b2  = (const float*)d_in[7];
    float* out = (float*)d_out;

    float* buf1; cudaGetSymbolAddress((void**)&buf1, g_buf1);
    float* buf2; cudaGetSymbolAddress((void**)&buf2, g_buf2);

    const int gemmBlocks = (N_ACT + 63) / 64;          // 4688
    const int ewBlocks   = (N_ACT * C / 4 + 255) / 256; // 37500
    const int statBlocks = (N_ACT + 255) / 256;        // 1172

    zero_all_k<<<1, 256>>>();
    rulebook_k<<<(N_ACT + 255) / 256, 256>>>(nbr);

    // ---- layer 1 ----
    gemm_center_k<<<gemmBlocks, 256>>>(x, nbr, W1 + 4 * C * C, buf1);
    gemm_scatter_k<<<dim3(gemmBlocks, NTAPS), 256>>>(x, W1, buf1);
    stats_k<<<statBlocks, 256>>>(buf1);
    finalize_k<<<1, C>>>(g1, b1);
    bnrelu_k<<<ewBlocks, 256>>>(buf1, buf2);
    zero_sums_k<<<1, 256>>>();

    // ---- layer 2 ----
    gemm_center_k<<<gemmBlocks, 256>>>(buf2, nbr, W2 + 4 * C * C, buf1);
    gemm_scatter_k<<<dim3(gemmBlocks, NTAPS), 256>>>(buf2, W2, buf1);
    stats_k<<<statBlocks, 256>>>(buf1);
    finalize_k<<<1, C>>>(g2, b2);
    final_k<<<ewBlocks, 256>>>(buf1, x, out);
}

// round 3
// speedup vs baseline: 1.6354x; 1.6354x over previous
#include <cuda_runtime.h>
#include <cstdint>

#define N_ACT 300000
#define Cc 128
#define NTAPS 8
#define EPSV 1e-4f

// ---------------- scratch (device globals) ----------------------------------
__device__ float g_buf1[N_ACT * Cc];
__device__ float g_buf2[N_ACT * Cc];
__device__ int   g_pin [NTAPS * N_ACT];
__device__ int   g_pout[NTAPS * N_ACT];
__device__ int   g_cnt [NTAPS];
__device__ float g_sum[Cc], g_sq[Cc];
__device__ float g_scale[Cc], g_shift[Cc];

// ---------------- helpers ----------------------------------------------------
__device__ __forceinline__ float tf32r(float x) {
    uint32_t y;
    asm("cvt.rna.tf32.f32 %0, %1;" : "=r"(y) : "f"(x));
    return __uint_as_float(y);
}

__device__ __forceinline__ void mma8(float* d, const uint32_t* a, const uint32_t* b) {
    asm volatile(
        "mma.sync.aligned.m16n8k8.row.col.f32.tf32.tf32.f32 "
        "{%0,%1,%2,%3}, {%4,%5,%6,%7}, {%8,%9}, {%0,%1,%2,%3};"
        : "+f"(d[0]), "+f"(d[1]), "+f"(d[2]), "+f"(d[3])
        : "r"(a[0]), "r"(a[1]), "r"(a[2]), "r"(a[3]), "r"(b[0]), "r"(b[1]));
}

// SMEM strides (floats): conflict-free fragment reads
#define WS_STRIDE 136   // Ws[k][n], 128 x 136
#define AS_STRIDE 36    // As[m][k], 128 x 36

// ---------------- utility kernels --------------------------------------------
__global__ void zero_all_k() {
    int t = threadIdx.x;
    if (t < NTAPS) g_cnt[t] = 0;
    if (t < Cc) { g_sum[t] = 0.f; g_sq[t] = 0.f; }
}
__global__ void zero_sums_k() {
    int t = threadIdx.x;
    if (t < Cc) { g_sum[t] = 0.f; g_sq[t] = 0.f; }
}

__global__ void rulebook_k(const int* __restrict__ nbr) {
    int i = blockIdx.x * blockDim.x + threadIdx.x;
    if (i >= N_ACT) return;
#pragma unroll
    for (int k = 0; k < 9; k++) {
        if (k == 4) continue;
        int idx = nbr[i * 9 + k];
        if (idx >= 0) {
            int t = (k < 4) ? k : k - 1;
            int p = atomicAdd(&g_cnt[t], 1);
            g_pin [t * N_ACT + p] = idx;
            g_pout[t * N_ACT + p] = i;
        }
    }
}

// ---------------- tf32 mma.sync GEMM ------------------------------------------
// CTA tile 128(m) x 128(n), K=128 in 4 chunks of 32.
// 8 warps: wm = wid>>1 (4 m-slices of 32), wn = wid&1 (2 n-slices of 64).
// Per warp: 2 m-frags x 8 n-frags of m16n8k8.
template <bool CENTER>
__global__ void __launch_bounds__(256, 2) conv_mma_k(
    const float* __restrict__ in, const float* __restrict__ W,
    float* __restrict__ out)
{
    extern __shared__ float smem[];
    float* Ws = smem;                          // 128*136
    float* As = smem + 128 * WS_STRIDE;        // 128*36
    int*   rin  = (int*)(As + 128 * AS_STRIDE);
    int*   rout = rin + 128;

    int tid = threadIdx.x;
    int wid = tid >> 5, lane = tid & 31;
    int wm = wid >> 1, wn = wid & 1;
    int grp = lane >> 2, tig = lane & 3;

    const float* Wk;
    const int *pin = nullptr, *pout = nullptr;
    int cnt;
    if (CENTER) {
        Wk = W;                       // center tap weight, rows are identity
        cnt = N_ACT;
    } else {
        int tap = blockIdx.y;
        cnt = g_cnt[tap];
        int kk = (tap < 4) ? tap : tap + 1;
        Wk = W + (long)kk * Cc * Cc;
        pin  = g_pin  + (long)tap * N_ACT;
        pout = g_pout + (long)tap * N_ACT;
    }

    // Stage W[k][n] -> Ws (tf32), once per CTA.
    for (int i = tid; i < 128 * 32; i += 256) {
        int k = i >> 5, n4 = (i & 31) * 4;
        float4 v = *(const float4*)&Wk[k * Cc + n4];
        float* d = &Ws[k * WS_STRIDE + n4];
        d[0] = tf32r(v.x); d[1] = tf32r(v.y); d[2] = tf32r(v.z); d[3] = tf32r(v.w);
    }

    int numTiles = (cnt + 127) >> 7;

    for (int tile = blockIdx.x; tile < numTiles; tile += gridDim.x) {
        int m0 = tile << 7;

        __syncthreads();   // prior epilogue done before rin/rout rewrite
        if (!CENTER && tid < 128) {
            int m = m0 + tid;
            rin[tid]  = (m < cnt) ? pin[m]  : -1;
            rout[tid] = (m < cnt) ? pout[m] : -1;
        }

        float acc[2][8][4];
#pragma unroll
        for (int a = 0; a < 2; a++)
#pragma unroll
            for (int b = 0; b < 8; b++)
#pragma unroll
                for (int c = 0; c < 4; c++) acc[a][b][c] = 0.f;

#pragma unroll
        for (int kc = 0; kc < 4; kc++) {
            __syncthreads();
            // gather A chunk: 128 rows x 32 cols
#pragma unroll
            for (int l = 0; l < 4; l++) {
                int idx = tid + l * 256;
                int rloc = idx >> 3, c4 = (idx & 7) * 4;
                int rg;
                if (CENTER) { int m = m0 + rloc; rg = (m < N_ACT) ? m : -1; }
                else        rg = rin[rloc];
                float4 v = make_float4(0.f, 0.f, 0.f, 0.f);
                if (rg >= 0) v = *(const float4*)&in[(long)rg * Cc + kc * 32 + c4];
                float* d = &As[rloc * AS_STRIDE + c4];
                d[0] = tf32r(v.x); d[1] = tf32r(v.y); d[2] = tf32r(v.z); d[3] = tf32r(v.w);
            }
            __syncthreads();

#pragma unroll
            for (int ks = 0; ks < 4; ks++) {
                int k0 = ks * 8;
                uint32_t afr[2][4], bfr[8][2];
#pragma unroll
                for (int mt = 0; mt < 2; mt++) {
                    int rb = wm * 32 + mt * 16;
                    afr[mt][0] = __float_as_uint(As[(rb + grp)     * AS_STRIDE + k0 + tig]);
                    afr[mt][1] = __float_as_uint(As[(rb + grp + 8) * AS_STRIDE + k0 + tig]);
                    afr[mt][2] = __float_as_uint(As[(rb + grp)     * AS_STRIDE + k0 + tig + 4]);
                    afr[mt][3] = __float_as_uint(As[(rb + grp + 8) * AS_STRIDE + k0 + tig + 4]);
                }
                int kg = kc * 32 + k0;
#pragma unroll
                for (int nt = 0; nt < 8; nt++) {
                    int col = wn * 64 + nt * 8 + grp;
                    bfr[nt][0] = __float_as_uint(Ws[(kg + tig)     * WS_STRIDE + col]);
                    bfr[nt][1] = __float_as_uint(Ws[(kg + tig + 4) * WS_STRIDE + col]);
                }
#pragma unroll
                for (int mt = 0; mt < 2; mt++)
#pragma unroll
                    for (int nt = 0; nt < 8; nt++)
                        mma8(acc[mt][nt], afr[mt], bfr[nt]);
            }
        }

        // epilogue
#pragma unroll
        for (int mt = 0; mt < 2; mt++) {
            int r0 = wm * 32 + mt * 16 + grp;
            int r1 = r0 + 8;
            if (CENTER) {
                int m0r = m0 + r0, m1r = m0 + r1;
#pragma unroll
                for (int nt = 0; nt < 8; nt++) {
                    int col = wn * 64 + nt * 8 + tig * 2;
                    if (m0r < N_ACT)
                        *(float2*)&out[(long)m0r * Cc + col] =
                            make_float2(acc[mt][nt][0], acc[mt][nt][1]);
                    if (m1r < N_ACT)
                        *(float2*)&out[(long)m1r * Cc + col] =
                            make_float2(acc[mt][nt][2], acc[mt][nt][3]);
                }
            } else {
                int ro0 = rout[r0], ro1 = rout[r1];
#pragma unroll
                for (int nt = 0; nt < 8; nt++) {
                    int col = wn * 64 + nt * 8 + tig * 2;
                    if (ro0 >= 0) {
                        atomicAdd(&out[(long)ro0 * Cc + col],     acc[mt][nt][0]);
                        atomicAdd(&out[(long)ro0 * Cc + col + 1], acc[mt][nt][1]);
                    }
                    if (ro1 >= 0) {
                        atomicAdd(&out[(long)ro1 * Cc + col],     acc[mt][nt][2]);
                        atomicAdd(&out[(long)ro1 * Cc + col + 1], acc[mt][nt][3]);
                    }
                }
            }
        }
    }
}

// ---------------- per-channel sum / sum-of-squares --------------------------
__global__ __launch_bounds__(256) void stats_k(const float* __restrict__ y) {
    int c4 = threadIdx.x & 31;
    int rbase = blockIdx.x * 256 + (threadIdx.x >> 5);
    float4 s = make_float4(0.f, 0.f, 0.f, 0.f);
    float4 q = make_float4(0.f, 0.f, 0.f, 0.f);
#pragma unroll 4
    for (int it = 0; it < 32; it++) {
        int r = rbase + it * 8;
        if (r < N_ACT) {
            float4 v = *(const float4*)&y[(long)r * Cc + c4 * 4];
            s.x += v.x; s.y += v.y; s.z += v.z; s.w += v.w;
            q.x += v.x * v.x; q.y += v.y * v.y; q.z += v.z * v.z; q.w += v.w * v.w;
        }
    }
    int c = c4 * 4;
    atomicAdd(&g_sum[c + 0], s.x); atomicAdd(&g_sum[c + 1], s.y);
    atomicAdd(&g_sum[c + 2], s.z); atomicAdd(&g_sum[c + 3], s.w);
    atomicAdd(&g_sq [c + 0], q.x); atomicAdd(&g_sq [c + 1], q.y);
    atomicAdd(&g_sq [c + 2], q.z); atomicAdd(&g_sq [c + 3], q.w);
}

__global__ void finalize_k(const float* __restrict__ gamma, const float* __restrict__ beta) {
    int c = threadIdx.x;
    float mean = g_sum[c] * (1.f / N_ACT);
    float var  = g_sq[c] * (1.f / N_ACT) - mean * mean;
    float istd = rsqrtf(var + EPSV);
    float sc = gamma[c] * istd;
    g_scale[c] = sc;
    g_shift[c] = beta[c] - mean * sc;
}

__global__ __launch_bounds__(256) void bnrelu_k(const float* __restrict__ in, float* __restrict__ outp) {
    int i = blockIdx.x * blockDim.x + threadIdx.x;
    if (i >= N_ACT * Cc / 4) return;
    int c4 = (i & 31) * 4;
    float4 v  = ((const float4*)in)[i];
    float4 sc = *(const float4*)&g_scale[c4];
    float4 sh = *(const float4*)&g_shift[c4];
    float4 o;
    o.x = fmaxf(v.x * sc.x + sh.x, 0.f);
    o.y = fmaxf(v.y * sc.y + sh.y, 0.f);
    o.z = fmaxf(v.z * sc.z + sh.z, 0.f);
    o.w = fmaxf(v.w * sc.w + sh.w, 0.f);
    ((float4*)outp)[i] = o;
}

__global__ __launch_bounds__(256) void final_k(
    const float* __restrict__ y, const float* __restrict__ x, float* __restrict__ outp)
{
    int i = blockIdx.x * blockDim.x + threadIdx.x;
    if (i >= N_ACT * Cc / 4) return;
    int c4 = (i & 31) * 4;
    float4 v  = ((const float4*)y)[i];
    float4 xv = ((const float4*)x)[i];
    float4 sc = *(const float4*)&g_scale[c4];
    float4 sh = *(const float4*)&g_shift[c4];
    float4 o;
    o.x = fmaxf(v.x * sc.x + sh.x + xv.x, 0.f);
    o.y = fmaxf(v.y * sc.y + sh.y + xv.y, 0.f);
    o.z = fmaxf(v.z * sc.z + sh.z + xv.z, 0.f);
    o.w = fmaxf(v.w * sc.w + sh.w + xv.w, 0.f);
    ((float4*)outp)[i] = o;
}

// ---------------- launch ------------------------------------------------------
extern "C" void kernel_launch(void* const* d_in, const int* in_sizes, int n_in,
                              void* d_out, int out_size)
{
    const float* x   = (const float*)d_in[0];
    const int*   nbr = (const int*)  d_in[1];
    const float* W1  = (const float*)d_in[2];
    const float* g1  = (const float*)d_in[3];
    const float* b1  = (const float*)d_in[4];
    const float* W2  = (const float*)d_in[5];
    const float* g2  = (const float*)d_in[6];
    const float* b2  = (const float*)d_in[7];
    float* out = (float*)d_out;

    float* buf1; cudaGetSymbolAddress((void**)&buf1, g_buf1);
    float* buf2; cudaGetSymbolAddress((void**)&buf2, g_buf2);

    const int SMEM = (128 * WS_STRIDE + 128 * AS_STRIDE) * 4 + 2 * 128 * 4;
    cudaFuncSetAttribute(conv_mma_k<true>,  cudaFuncAttributeMaxDynamicSharedMemorySize, SMEM);
    cudaFuncSetAttribute(conv_mma_k<false>, cudaFuncAttributeMaxDynamicSharedMemorySize, SMEM);

    const int ewBlocks   = (N_ACT * Cc / 4 + 255) / 256;
    const int statBlocks = (N_ACT + 255) / 256;

    zero_all_k<<<1, 256>>>();
    rulebook_k<<<(N_ACT + 255) / 256, 256>>>(nbr);

    // ---- layer 1 ----
    conv_mma_k<true ><<<296, 256, SMEM>>>(x, W1 + 4 * Cc * Cc, buf1);
    conv_mma_k<false><<<dim3(37, NTAPS), 256, SMEM>>>(x, W1, buf1);
    stats_k<<<statBlocks, 256>>>(buf1);
    finalize_k<<<1, Cc>>>(g1, b1);
    bnrelu_k<<<ewBlocks, 256>>>(buf1, buf2);
    zero_sums_k<<<1, 256>>>();

    // ---- layer 2 ----
    conv_mma_k<true ><<<296, 256, SMEM>>>(buf2, W2 + 4 * Cc * Cc, buf1);
    conv_mma_k<false><<<dim3(37, NTAPS), 256, SMEM>>>(buf2, W2, buf1);
    stats_k<<<statBlocks, 256>>>(buf1);
    finalize_k<<<1, Cc>>>(g2, b2);
    final_k<<<ewBlocks, 256>>>(buf1, x, out);
}

// round 4
// speedup vs baseline: 1.7935x; 1.0967x over previous
#include <cuda_runtime.h>
#include <cstdint>

#define N_ACT 300000
#define Cc 128
#define NTAPS 8
#define EPSV 1e-4f

// ---------------- scratch (device globals) ----------------------------------
__device__ float g_buf1[N_ACT * Cc];
__device__ float g_buf2[N_ACT * Cc];
__device__ int   g_pin [NTAPS * N_ACT];
__device__ int   g_pout[NTAPS * N_ACT];
__device__ int   g_cnt [NTAPS];
__device__ float g_sum[Cc], g_sq[Cc];
__device__ float g_scale[Cc], g_shift[Cc];

// ---------------- helpers ----------------------------------------------------
__device__ __forceinline__ uint32_t tf32u(float x) {
    uint32_t y;
    asm("cvt.rna.tf32.f32 %0, %1;" : "=r"(y) : "f"(x));
    return y;
}
__device__ __forceinline__ float tf32r(float x) { return __uint_as_float(tf32u(x)); }

__device__ __forceinline__ void mma8(float* d, const uint32_t* a, const uint32_t* b) {
    asm volatile(
        "mma.sync.aligned.m16n8k8.row.col.f32.tf32.tf32.f32 "
        "{%0,%1,%2,%3}, {%4,%5,%6,%7}, {%8,%9}, {%0,%1,%2,%3};"
        : "+f"(d[0]), "+f"(d[1]), "+f"(d[2]), "+f"(d[3])
        : "r"(a[0]), "r"(a[1]), "r"(a[2]), "r"(a[3]), "r"(b[0]), "r"(b[1]));
}

__device__ __forceinline__ uint32_t smem_u32(const void* p) {
    uint32_t a;
    asm("{ .reg .u64 t; cvta.to.shared.u64 t, %1; cvt.u32.u64 %0, t; }" : "=r"(a) : "l"(p));
    return a;
}

// SMEM strides (floats): conflict-free fragment reads
#define WS_STRIDE 136   // Ws[k][n], 128 x 136
#define AS_STRIDE 36    // As[m][k], 128 x 36 (row = 144B, 16B-aligned for cp.async)
#define AS_STAGE  (128 * AS_STRIDE)   // floats per stage

// ---------------- utility kernels --------------------------------------------
__global__ void zero_all_k() {
    int t = threadIdx.x;
    if (t < NTAPS) g_cnt[t] = 0;
    if (t < Cc) { g_sum[t] = 0.f; g_sq[t] = 0.f; }
}
__global__ void zero_sums_k() {
    int t = threadIdx.x;
    if (t < Cc) { g_sum[t] = 0.f; g_sq[t] = 0.f; }
}

// warp-aggregated rulebook build
__global__ void rulebook_k(const int* __restrict__ nbr) {
    int i = blockIdx.x * blockDim.x + threadIdx.x;
    bool act = (i < N_ACT);
    int lane = threadIdx.x & 31;
#pragma unroll
    for (int k = 0; k < 9; k++) {
        if (k == 4) continue;
        int idx = act ? nbr[i * 9 + k] : -1;
        bool valid = idx >= 0;
        unsigned mask = __ballot_sync(0xffffffffu, valid);
        if (valid) {
            int t = (k < 4) ? k : k - 1;
            int leader = __ffs(mask) - 1;
            int base = 0;
            if (lane == leader) base = atomicAdd(&g_cnt[t], __popc(mask));
            base = __shfl_sync(mask, base, leader);
            int pos = base + __popc(mask & ((1u << lane) - 1u));
            g_pin [t * N_ACT + pos] = idx;
            g_pout[t * N_ACT + pos] = i;
        }
    }
}

// ---------------- tf32 mma.sync GEMM with cp.async 2-stage pipeline ----------
// CTA tile 128(m) x 128(n), K=128 in 4 chunks of 32.
// 8 warps: wm = wid>>1 (4 m-slices of 32), wn = wid&1 (2 n-slices of 64).
template <bool CENTER, bool BN>
__global__ void __launch_bounds__(256, 2) conv_mma_k(
    const float* __restrict__ in, const float* __restrict__ W,
    float* __restrict__ out)
{
    extern __shared__ float smem[];
    float* Ws = smem;                                  // 128*136
    float* As = smem + 128 * WS_STRIDE;                // 2 stages x 128*36
    int*   rin  = (int*)(As + 2 * AS_STAGE);
    int*   rout = rin + 128;
    float* ssc  = (float*)(rout + 128);                // scale[128]
    float* ssh  = ssc + 128;                           // shift[128]

    const uint32_t asu = smem_u32(As);

    int tid = threadIdx.x;
    int wid = tid >> 5, lane = tid & 31;
    int wm = wid >> 1, wn = wid & 1;
    int grp = lane >> 2, tig = lane & 3;

    const float* Wk;
    const int *pin = nullptr, *pout = nullptr;
    int cnt;
    if (CENTER) {
        Wk = W;
        cnt = N_ACT;
    } else {
        int tap = blockIdx.y;
        cnt = g_cnt[tap];
        int kk = (tap < 4) ? tap : tap + 1;
        Wk = W + (long)kk * Cc * Cc;
        pin  = g_pin  + (long)tap * N_ACT;
        pout = g_pout + (long)tap * N_ACT;
    }

    // Stage W[k][n] -> Ws (tf32), once per CTA.
    for (int i = tid; i < 128 * 32; i += 256) {
        int k = i >> 5, n4 = (i & 31) * 4;
        float4 v = *(const float4*)&Wk[k * Cc + n4];
        float* d = &Ws[k * WS_STRIDE + n4];
        d[0] = tf32r(v.x); d[1] = tf32r(v.y); d[2] = tf32r(v.z); d[3] = tf32r(v.w);
    }
    if (BN && tid < 128) { ssc[tid] = g_scale[tid]; ssh[tid] = g_shift[tid]; }

    int numTiles = (cnt + 127) >> 7;

    for (int tile = blockIdx.x; tile < numTiles; tile += gridDim.x) {
        int m0 = tile << 7;

        __syncthreads();   // prior tile fully consumed
        if (!CENTER && tid < 128) {
            int m = m0 + tid;
            rin[tid]  = (m < cnt) ? pin[m]  : -1;
            rout[tid] = (m < cnt) ? pout[m] : -1;
        }
        __syncthreads();

        // issue one 128x32 chunk into a stage via cp.async
        auto issue = [&](int kc, int stage) {
            uint32_t sbase = asu + (uint32_t)stage * (AS_STAGE * 4);
#pragma unroll
            for (int l = 0; l < 4; l++) {
                int idx = tid + l * 256;          // 0..1023 16B-chunks
                int rloc = idx >> 3, c16 = idx & 7;
                int rg;
                if (CENTER) { int m = m0 + rloc; rg = (m < N_ACT) ? m : -1; }
                else        rg = rin[rloc];
                const float* src = in + (long)(rg < 0 ? 0 : rg) * Cc + kc * 32 + c16 * 4;
                uint32_t dst = sbase + (uint32_t)(rloc * 144 + c16 * 16);
                int sz = (rg >= 0) ? 16 : 0;
                asm volatile("cp.async.ca.shared.global [%0], [%1], 16, %2;"
                             :: "r"(dst), "l"(src), "r"(sz));
            }
            asm volatile("cp.async.commit_group;" ::: "memory");
        };

        issue(0, 0);

        float acc[2][8][4];
#pragma unroll
        for (int a = 0; a < 2; a++)
#pragma unroll
            for (int b = 0; b < 8; b++)
#pragma unroll
                for (int c = 0; c < 4; c++) acc[a][b][c] = 0.f;

#pragma unroll
        for (int kc = 0; kc < 4; kc++) {
            if (kc < 3) issue(kc + 1, (kc + 1) & 1);

            if (kc < 3) asm volatile("cp.async.wait_group 1;" ::: "memory");
            else        asm volatile("cp.async.wait_group 0;" ::: "memory");
            __syncthreads();

            const float* Ast = As + (kc & 1) * AS_STAGE;

#pragma unroll
            for (int ks = 0; ks < 4; ks++) {
                int k0 = ks * 8;
                int ka = kc * 32 + k0 + tig;      // global channel of afr[ ][0/1]
                int kb = ka + 4;                  // channel of afr[ ][2/3]
                float sca = 0.f, sha = 0.f, scb = 0.f, shb = 0.f;
                if (BN) { sca = ssc[ka]; sha = ssh[ka]; scb = ssc[kb]; shb = ssh[kb]; }

                uint32_t afr[2][4], bfr[8][2];
#pragma unroll
                for (int mt = 0; mt < 2; mt++) {
                    int rb = wm * 32 + mt * 16;
                    float e0 = Ast[(rb + grp)     * AS_STRIDE + k0 + tig];
                    float e1 = Ast[(rb + grp + 8) * AS_STRIDE + k0 + tig];
                    float e2 = Ast[(rb + grp)     * AS_STRIDE + k0 + tig + 4];
                    float e3 = Ast[(rb + grp + 8) * AS_STRIDE + k0 + tig + 4];
                    if (BN) {
                        e0 = fmaxf(e0 * sca + sha, 0.f);
                        e1 = fmaxf(e1 * sca + sha, 0.f);
                        e2 = fmaxf(e2 * scb + shb, 0.f);
                        e3 = fmaxf(e3 * scb + shb, 0.f);
                    }
                    afr[mt][0] = tf32u(e0); afr[mt][1] = tf32u(e1);
                    afr[mt][2] = tf32u(e2); afr[mt][3] = tf32u(e3);
                }
                int kg = kc * 32 + k0;
#pragma unroll
                for (int nt = 0; nt < 8; nt++) {
                    int col = wn * 64 + nt * 8 + grp;
                    bfr[nt][0] = __float_as_uint(Ws[(kg + tig)     * WS_STRIDE + col]);
                    bfr[nt][1] = __float_as_uint(Ws[(kg + tig + 4) * WS_STRIDE + col]);
                }
#pragma unroll
                for (int mt = 0; mt < 2; mt++)
#pragma unroll
                    for (int nt = 0; nt < 8; nt++)
                        mma8(acc[mt][nt], afr[mt], bfr[nt]);
            }
            __syncthreads();
        }

        // epilogue
#pragma unroll
        for (int mt = 0; mt < 2; mt++) {
            int r0 = wm * 32 + mt * 16 + grp;
            int r1 = r0 + 8;
            if (CENTER) {
                int m0r = m0 + r0, m1r = m0 + r1;
#pragma unroll
                for (int nt = 0; nt < 8; nt++) {
                    int col = wn * 64 + nt * 8 + tig * 2;
                    if (m0r < N_ACT)
                        *(float2*)&out[(long)m0r * Cc + col] =
                            make_float2(acc[mt][nt][0], acc[mt][nt][1]);
                    if (m1r < N_ACT)
                        *(float2*)&out[(long)m1r * Cc + col] =
                            make_float2(acc[mt][nt][2], acc[mt][nt][3]);
                }
            } else {
                int ro0 = rout[r0], ro1 = rout[r1];
#pragma unroll
                for (int nt = 0; nt < 8; nt++) {
                    int col = wn * 64 + nt * 8 + tig * 2;
                    if (ro0 >= 0) {
                        atomicAdd(&out[(long)ro0 * Cc + col],     acc[mt][nt][0]);
                        atomicAdd(&out[(long)ro0 * Cc + col + 1], acc[mt][nt][1]);
                    }
                    if (ro1 >= 0) {
                        atomicAdd(&out[(long)ro1 * Cc + col],     acc[mt][nt][2]);
                        atomicAdd(&out[(long)ro1 * Cc + col + 1], acc[mt][nt][3]);
                    }
                }
            }
        }
    }
}

// ---------------- per-channel sum / sum-of-squares --------------------------
__global__ __launch_bounds__(256) void stats_k(const float* __restrict__ y) {
    int c4 = threadIdx.x & 31;
    int rbase = blockIdx.x * 256 + (threadIdx.x >> 5);
    float4 s = make_float4(0.f, 0.f, 0.f, 0.f);
    float4 q = make_float4(0.f, 0.f, 0.f, 0.f);
#pragma unroll 4
    for (int it = 0; it < 32; it++) {
        int r = rbase + it * 8;
        if (r < N_ACT) {
            float4 v = *(const float4*)&y[(long)r * Cc + c4 * 4];
            s.x += v.x; s.y += v.y; s.z += v.z; s.w += v.w;
            q.x += v.x * v.x; q.y += v.y * v.y; q.z += v.z * v.z; q.w += v.w * v.w;
        }
    }
    int c = c4 * 4;
    atomicAdd(&g_sum[c + 0], s.x); atomicAdd(&g_sum[c + 1], s.y);
    atomicAdd(&g_sum[c + 2], s.z); atomicAdd(&g_sum[c + 3], s.w);
    atomicAdd(&g_sq [c + 0], q.x); atomicAdd(&g_sq [c + 1], q.y);
    atomicAdd(&g_sq [c + 2], q.z); atomicAdd(&g_sq [c + 3], q.w);
}

__global__ void finalize_k(const float* __restrict__ gamma, const float* __restrict__ beta) {
    int c = threadIdx.x;
    float mean = g_sum[c] * (1.f / N_ACT);
    float var  = g_sq[c] * (1.f / N_ACT) - mean * mean;
    float istd = rsqrtf(var + EPSV);
    float sc = gamma[c] * istd;
    g_scale[c] = sc;
    g_shift[c] = beta[c] - mean * sc;
}

__global__ __launch_bounds__(256) void final_k(
    const float* __restrict__ y, const float* __restrict__ x, float* __restrict__ outp)
{
    int i = blockIdx.x * blockDim.x + threadIdx.x;
    if (i >= N_ACT * Cc / 4) return;
    int c4 = (i & 31) * 4;
    float4 v  = ((const float4*)y)[i];
    float4 xv = ((const float4*)x)[i];
    float4 sc = *(const float4*)&g_scale[c4];
    float4 sh = *(const float4*)&g_shift[c4];
    float4 o;
    o.x = fmaxf(v.x * sc.x + sh.x + xv.x, 0.f);
    o.y = fmaxf(v.y * sc.y + sh.y + xv.y, 0.f);
    o.z = fmaxf(v.z * sc.z + sh.z + xv.z, 0.f);
    o.w = fmaxf(v.w * sc.w + sh.w + xv.w, 0.f);
    ((float4*)outp)[i] = o;
}

// ---------------- launch ------------------------------------------------------
extern "C" void kernel_launch(void* const* d_in, const int* in_sizes, int n_in,
                              void* d_out, int out_size)
{
    const float* x   = (const float*)d_in[0];
    const int*   nbr = (const int*)  d_in[1];
    const float* W1  = (const float*)d_in[2];
    const float* g1  = (const float*)d_in[3];
    const float* b1  = (const float*)d_in[4];
    const float* W2  = (const float*)d_in[5];
    const float* g2  = (const float*)d_in[6];
    const float* b2  = (const float*)d_in[7];
    float* out = (float*)d_out;

    float* buf1; cudaGetSymbolAddress((void**)&buf1, g_buf1);
    float* buf2; cudaGetSymbolAddress((void**)&buf2, g_buf2);

    const int SMEM = (128 * WS_STRIDE + 2 * AS_STAGE) * 4 + 2 * 128 * 4 + 2 * 128 * 4;
    cudaFuncSetAttribute(conv_mma_k<true,  false>, cudaFuncAttributeMaxDynamicSharedMemorySize, SMEM);
    cudaFuncSetAttribute(conv_mma_k<false, false>, cudaFuncAttributeMaxDynamicSharedMemorySize, SMEM);
    cudaFuncSetAttribute(conv_mma_k<true,  true >, cudaFuncAttributeMaxDynamicSharedMemorySize, SMEM);
    cudaFuncSetAttribute(conv_mma_k<false, true >, cudaFuncAttributeMaxDynamicSharedMemorySize, SMEM);

    const int ewBlocks   = (N_ACT * Cc / 4 + 255) / 256;
    const int statBlocks = (N_ACT + 255) / 256;

    zero_all_k<<<1, 256>>>();
    rulebook_k<<<(N_ACT + 255) / 256, 256>>>(nbr);

    // ---- layer 1 (no BN on input) ----
    conv_mma_k<true,  false><<<296, 256, SMEM>>>(x, W1 + 4 * Cc * Cc, buf1);
    conv_mma_k<false, false><<<dim3(37, NTAPS), 256, SMEM>>>(x, W1, buf1);
    stats_k<<<statBlocks, 256>>>(buf1);
    finalize_k<<<1, Cc>>>(g1, b1);
    zero_sums_k<<<1, 256>>>();

    // ---- layer 2 (BN+ReLU of layer 1 fused into A loads) ----
    conv_mma_k<true,  true ><<<296, 256, SMEM>>>(buf1, W2 + 4 * Cc * Cc, buf2);
    conv_mma_k<false, true ><<<dim3(37, NTAPS), 256, SMEM>>>(buf1, W2, buf2);
    stats_k<<<statBlocks, 256>>>(buf2);
    finalize_k<<<1, Cc>>>(g2, b2);
    final_k<<<ewBlocks, 256>>>(buf2, x, out);
}

// round 5
// speedup vs baseline: 1.8027x; 1.0052x over previous
#include <cuda_runtime.h>
#include <cstdint>

#define N_ACT 300000
#define Cc 128
#define NTAPS 8
#define EPSV 1e-4f

// ---------------- scratch (device globals) ----------------------------------
__device__ float g_buf1[N_ACT * Cc];
__device__ float g_buf2[N_ACT * Cc];
__device__ int   g_pin [NTAPS * N_ACT];
__device__ int   g_pout[NTAPS * N_ACT];
__device__ int   g_cnt [NTAPS];
__device__ float g_sum[Cc], g_sq[Cc];
__device__ float g_scale[Cc], g_shift[Cc];

// ---------------- helpers ----------------------------------------------------
__device__ __forceinline__ uint32_t tf32u(float x) {
    uint32_t y;
    asm("cvt.rna.tf32.f32 %0, %1;" : "=r"(y) : "f"(x));
    return y;
}
__device__ __forceinline__ float tf32r(float x) { return __uint_as_float(tf32u(x)); }

__device__ __forceinline__ void mma8(float* d, const uint32_t* a, const uint32_t* b) {
    asm volatile(
        "mma.sync.aligned.m16n8k8.row.col.f32.tf32.tf32.f32 "
        "{%0,%1,%2,%3}, {%4,%5,%6,%7}, {%8,%9}, {%0,%1,%2,%3};"
        : "+f"(d[0]), "+f"(d[1]), "+f"(d[2]), "+f"(d[3])
        : "r"(a[0]), "r"(a[1]), "r"(a[2]), "r"(a[3]), "r"(b[0]), "r"(b[1]));
}

__device__ __forceinline__ uint32_t smem_u32(const void* p) {
    uint32_t a;
    asm("{ .reg .u64 t; cvta.to.shared.u64 t, %1; cvt.u32.u64 %0, t; }" : "=r"(a) : "l"(p));
    return a;
}

// SMEM geometry
#define WP_STRIDE 132                  // float2 units per (s,tig) row of Wpair
#define WP_FLOATS (16 * 4 * WP_STRIDE * 2)   // 16896 floats = 67.6KB
#define AS_STRIDE 36                   // floats per A row (144B, 16B aligned)
#define AS_STAGE  (128 * AS_STRIDE)

// ---------------- utility kernels --------------------------------------------
__global__ void zero_all_k() {
    int t = threadIdx.x;
    if (t < NTAPS) g_cnt[t] = 0;
    if (t < Cc) { g_sum[t] = 0.f; g_sq[t] = 0.f; }
}

// warp-aggregated rulebook build
__global__ void rulebook_k(const int* __restrict__ nbr) {
    int i = blockIdx.x * blockDim.x + threadIdx.x;
    bool act = (i < N_ACT);
    int lane = threadIdx.x & 31;
#pragma unroll
    for (int k = 0; k < 9; k++) {
        if (k == 4) continue;
        int idx = act ? nbr[i * 9 + k] : -1;
        bool valid = idx >= 0;
        unsigned mask = __ballot_sync(0xffffffffu, valid);
        if (valid) {
            int t = (k < 4) ? k : k - 1;
            int leader = __ffs(mask) - 1;
            int base = 0;
            if (lane == leader) base = atomicAdd(&g_cnt[t], __popc(mask));
            base = __shfl_sync(mask, base, leader);
            int pos = base + __popc(mask & ((1u << lane) - 1u));
            g_pin [t * N_ACT + pos] = idx;
            g_pout[t * N_ACT + pos] = i;
        }
    }
}

// ---------------- tf32 mma.sync GEMM with cp.async 2-stage pipeline ----------
// CTA tile 128(m) x 128(n), K=128 in 4 chunks of 32.
// 8 warps: wm = wid>>1 (4 m-slices of 32), wn = wid&1 (2 n-slices of 64).
// B staged as paired float2 {W[8s+tig][n], W[8s+tig+4][n]} -> single LDS.64.
template <bool CENTER, bool BN>
__global__ void __launch_bounds__(256, 2) conv_mma_k(
    const float* __restrict__ in, const float* __restrict__ W,
    float* __restrict__ out)
{
    extern __shared__ float smem[];
    float2* Wp = (float2*)smem;                        // [16][4][WP_STRIDE]
    float*  As = smem + WP_FLOATS;                     // 2 stages x 128*36
    int*    rin  = (int*)(As + 2 * AS_STAGE);
    int*    rout = rin + 128;
    float*  ssc  = (float*)(rout + 128);
    float*  ssh  = ssc + 128;

    const uint32_t asu = smem_u32(As);

    int tid = threadIdx.x;
    int wid = tid >> 5, lane = tid & 31;
    int wm = wid >> 1, wn = wid & 1;
    int grp = lane >> 2, tig = lane & 3;

    const float* Wk;
    const int *pin = nullptr, *pout = nullptr;
    int cnt;
    if (CENTER) {
        Wk = W;
        cnt = N_ACT;
    } else {
        int tap = blockIdx.y;
        cnt = g_cnt[tap];
        int kk = (tap < 4) ? tap : tap + 1;
        Wk = W + (long)kk * Cc * Cc;
        pin  = g_pin  + (long)tap * N_ACT;
        pout = g_pout + (long)tap * N_ACT;
    }

    // Stage W[k][n] -> Wpair (tf32), once per CTA.
    for (int i = tid; i < 128 * 32; i += 256) {
        int k = i >> 5, n4 = (i & 31) * 4;
        float4 v = *(const float4*)&Wk[k * Cc + n4];
        int s = k >> 3, r = k & 7, t = r & 3, half = r >> 2;
        float* d = smem + (((s * 4 + t) * WP_STRIDE + n4) * 2 + half);
        d[0] = tf32r(v.x); d[2] = tf32r(v.y); d[4] = tf32r(v.z); d[6] = tf32r(v.w);
    }
    if (BN && tid < 128) { ssc[tid] = g_scale[tid]; ssh[tid] = g_shift[tid]; }

    int numTiles = (cnt + 127) >> 7;

    for (int tile = blockIdx.x; tile < numTiles; tile += gridDim.x) {
        int m0 = tile << 7;

        __syncthreads();   // prior tile fully consumed
        if (!CENTER && tid < 128) {
            int m = m0 + tid;
            rin[tid]  = (m < cnt) ? pin[m]  : -1;
            rout[tid] = (m < cnt) ? pout[m] : -1;
        }
        __syncthreads();

        auto issue = [&](int kc, int stage) {
            uint32_t sbase = asu + (uint32_t)stage * (AS_STAGE * 4);
#pragma unroll
            for (int l = 0; l < 4; l++) {
                int idx = tid + l * 256;          // 0..1023 16B-chunks
                int rloc = idx >> 3, c16 = idx & 7;
                int rg;
                if (CENTER) { int m = m0 + rloc; rg = (m < N_ACT) ? m : -1; }
                else        rg = rin[rloc];
                const float* src = in + (long)(rg < 0 ? 0 : rg) * Cc + kc * 32 + c16 * 4;
                uint32_t dst = sbase + (uint32_t)(rloc * 144 + c16 * 16);
                int sz = (rg >= 0) ? 16 : 0;
                asm volatile("cp.async.ca.shared.global [%0], [%1], 16, %2;"
                             :: "r"(dst), "l"(src), "r"(sz));
            }
            asm volatile("cp.async.commit_group;" ::: "memory");
        };

        issue(0, 0);

        float acc[2][8][4];
#pragma unroll
        for (int a = 0; a < 2; a++)
#pragma unroll
            for (int b = 0; b < 8; b++)
#pragma unroll
                for (int c = 0; c < 4; c++) acc[a][b][c] = 0.f;

#pragma unroll
        for (int kc = 0; kc < 4; kc++) {
            if (kc < 3) issue(kc + 1, (kc + 1) & 1);

            if (kc < 3) asm volatile("cp.async.wait_group 1;" ::: "memory");
            else        asm volatile("cp.async.wait_group 0;" ::: "memory");
            __syncthreads();

            const float* Ast = As + (kc & 1) * AS_STAGE;

#pragma unroll
            for (int ks = 0; ks < 4; ks++) {
                int k0 = ks * 8;
                int s  = kc * 4 + ks;
                int ka = kc * 32 + k0 + tig;
                int kb = ka + 4;
                float sca = 0.f, sha = 0.f, scb = 0.f, shb = 0.f;
                if (BN) { sca = ssc[ka]; sha = ssh[ka]; scb = ssc[kb]; shb = ssh[kb]; }

                uint32_t afr[2][4], bfr[8][2];
#pragma unroll
                for (int mt = 0; mt < 2; mt++) {
                    int rb = wm * 32 + mt * 16;
                    float e0 = Ast[(rb + grp)     * AS_STRIDE + k0 + tig];
                    float e1 = Ast[(rb + grp + 8) * AS_STRIDE + k0 + tig];
                    float e2 = Ast[(rb + grp)     * AS_STRIDE + k0 + tig + 4];
                    float e3 = Ast[(rb + grp + 8) * AS_STRIDE + k0 + tig + 4];
                    if (BN) {
                        e0 = fmaxf(e0 * sca + sha, 0.f);
                        e1 = fmaxf(e1 * sca + sha, 0.f);
                        e2 = fmaxf(e2 * scb + shb, 0.f);
                        e3 = fmaxf(e3 * scb + shb, 0.f);
                    }
                    afr[mt][0] = tf32u(e0); afr[mt][1] = tf32u(e1);
                    afr[mt][2] = tf32u(e2); afr[mt][3] = tf32u(e3);
                }
                const float2* wps = Wp + (s * 4 + tig) * WP_STRIDE;
#pragma unroll
                for (int nt = 0; nt < 8; nt++) {
                    int col = wn * 64 + nt * 8 + grp;
                    float2 p = wps[col];
                    bfr[nt][0] = __float_as_uint(p.x);
                    bfr[nt][1] = __float_as_uint(p.y);
                }
#pragma unroll
                for (int mt = 0; mt < 2; mt++)
#pragma unroll
                    for (int nt = 0; nt < 8; nt++)
                        mma8(acc[mt][nt], afr[mt], bfr[nt]);
            }
            __syncthreads();
        }

        // epilogue
#pragma unroll
        for (int mt = 0; mt < 2; mt++) {
            int r0 = wm * 32 + mt * 16 + grp;
            int r1 = r0 + 8;
            if (CENTER) {
                int m0r = m0 + r0, m1r = m0 + r1;
#pragma unroll
                for (int nt = 0; nt < 8; nt++) {
                    int col = wn * 64 + nt * 8 + tig * 2;
                    if (m0r < N_ACT)
                        *(float2*)&out[(long)m0r * Cc + col] =
                            make_float2(acc[mt][nt][0], acc[mt][nt][1]);
                    if (m1r < N_ACT)
                        *(float2*)&out[(long)m1r * Cc + col] =
                            make_float2(acc[mt][nt][2], acc[mt][nt][3]);
                }
            } else {
                int ro0 = rout[r0], ro1 = rout[r1];
#pragma unroll
                for (int nt = 0; nt < 8; nt++) {
                    int col = wn * 64 + nt * 8 + tig * 2;
                    if (ro0 >= 0) {
                        atomicAdd(&out[(long)ro0 * Cc + col],     acc[mt][nt][0]);
                        atomicAdd(&out[(long)ro0 * Cc + col + 1], acc[mt][nt][1]);
                    }
                    if (ro1 >= 0) {
                        atomicAdd(&out[(long)ro1 * Cc + col],     acc[mt][nt][2]);
                        atomicAdd(&out[(long)ro1 * Cc + col + 1], acc[mt][nt][3]);
                    }
                }
            }
        }
    }
}

// ---------------- per-channel sum / sum-of-squares --------------------------
__global__ __launch_bounds__(256) void stats_k(const float* __restrict__ y) {
    int c4 = threadIdx.x & 31;
    int rbase = blockIdx.x * 256 + (threadIdx.x >> 5);
    float4 s = make_float4(0.f, 0.f, 0.f, 0.f);
    float4 q = make_float4(0.f, 0.f, 0.f, 0.f);
#pragma unroll 4
    for (int it = 0; it < 32; it++) {
        int r = rbase + it * 8;
        if (r < N_ACT) {
            float4 v = *(const float4*)&y[(long)r * Cc + c4 * 4];
            s.x += v.x; s.y += v.y; s.z += v.z; s.w += v.w;
            q.x += v.x * v.x; q.y += v.y * v.y; q.z += v.z * v.z; q.w += v.w * v.w;
        }
    }
    int c = c4 * 4;
    atomicAdd(&g_sum[c + 0], s.x); atomicAdd(&g_sum[c + 1], s.y);
    atomicAdd(&g_sum[c + 2], s.z); atomicAdd(&g_sum[c + 3], s.w);
    atomicAdd(&g_sq [c + 0], q.x); atomicAdd(&g_sq [c + 1], q.y);
    atomicAdd(&g_sq [c + 2], q.z); atomicAdd(&g_sq [c + 3], q.w);
}

// computes scale/shift, then re-zeros the accumulators for the next use
__global__ void finalize_k(const float* __restrict__ gamma, const float* __restrict__ beta) {
    int c = threadIdx.x;
    float mean = g_sum[c] * (1.f / N_ACT);
    float var  = g_sq[c] * (1.f / N_ACT) - mean * mean;
    float istd = rsqrtf(var + EPSV);
    float sc = gamma[c] * istd;
    g_scale[c] = sc;
    g_shift[c] = beta[c] - mean * sc;
    g_sum[c] = 0.f;
    g_sq[c]  = 0.f;
}

__global__ __launch_bounds__(256) void final_k(
    const float* __restrict__ y, const float* __restrict__ x, float* __restrict__ outp)
{
    int i = blockIdx.x * blockDim.x + threadIdx.x;
    if (i >= N_ACT * Cc / 4) return;
    int c4 = (i & 31) * 4;
    float4 v  = ((const float4*)y)[i];
    float4 xv = ((const float4*)x)[i];
    float4 sc = *(const float4*)&g_scale[c4];
    float4 sh = *(const float4*)&g_shift[c4];
    float4 o;
    o.x = fmaxf(v.x * sc.x + sh.x + xv.x, 0.f);
    o.y = fmaxf(v.y * sc.y + sh.y + xv.y, 0.f);
    o.z = fmaxf(v.z * sc.z + sh.z + xv.z, 0.f);
    o.w = fmaxf(v.w * sc.w + sh.w + xv.w, 0.f);
    ((float4*)outp)[i] = o;
}

// ---------------- launch ------------------------------------------------------
extern "C" void kernel_launch(void* const* d_in, const int* in_sizes, int n_in,
                              void* d_out, int out_size)
{
    const float* x   = (const float*)d_in[0];
    const int*   nbr = (const int*)  d_in[1];
    const float* W1  = (const float*)d_in[2];
    const float* g1  = (const float*)d_in[3];
    const float* b1  = (const float*)d_in[4];
    const float* W2  = (const float*)d_in[5];
    const float* g2  = (const float*)d_in[6];
    const float* b2  = (const float*)d_in[7];
    float* out = (float*)d_out;

    float* buf1; cudaGetSymbolAddress((void**)&buf1, g_buf1);
    float* buf2; cudaGetSymbolAddress((void**)&buf2, g_buf2);

    const int SMEM = (WP_FLOATS + 2 * AS_STAGE) * 4 + 2 * 128 * 4 + 2 * 128 * 4;
    cudaFuncSetAttribute(conv_mma_k<true,  false>, cudaFuncAttributeMaxDynamicSharedMemorySize, SMEM);
    cudaFuncSetAttribute(conv_mma_k<false, false>, cudaFuncAttributeMaxDynamicSharedMemorySize, SMEM);
    cudaFuncSetAttribute(conv_mma_k<true,  true >, cudaFuncAttributeMaxDynamicSharedMemorySize, SMEM);
    cudaFuncSetAttribute(conv_mma_k<false, true >, cudaFuncAttributeMaxDynamicSharedMemorySize, SMEM);

    const int ewBlocks   = (N_ACT * Cc / 4 + 255) / 256;
    const int statBlocks = (N_ACT + 255) / 256;

    zero_all_k<<<1, 256>>>();
    rulebook_k<<<(N_ACT + 255) / 256, 256>>>(nbr);

    // ---- layer 1 (no BN on input) ----
    conv_mma_k<true,  false><<<304, 256, SMEM>>>(x, W1 + 4 * Cc * Cc, buf1);
    conv_mma_k<false, false><<<dim3(38, NTAPS), 256, SMEM>>>(x, W1, buf1);
    stats_k<<<statBlocks, 256>>>(buf1);
    finalize_k<<<1, Cc>>>(g1, b1);

    // ---- layer 2 (BN+ReLU of layer 1 fused into A loads) ----
    conv_mma_k<true,  true ><<<304, 256, SMEM>>>(buf1, W2 + 4 * Cc * Cc, buf2);
    conv_mma_k<false, true ><<<dim3(38, NTAPS), 256, SMEM>>>(buf1, W2, buf2);
    stats_k<<<statBlocks, 256>>>(buf2);
    finalize_k<<<1, Cc>>>(g2, b2);
    final_k<<<ewBlocks, 256>>>(buf2, x, out);
}

// round 6
// speedup vs baseline: 1.8481x; 1.0252x over previous
#include <cuda_runtime.h>
#include <cstdint>

#define N_ACT 300000
#define Cc 128
#define NTAPS 8
#define EPSV 1e-4f

// ---------------- scratch (device globals) ----------------------------------
__device__ float g_buf1[N_ACT * Cc];
__device__ float g_buf2[N_ACT * Cc];
__device__ int   g_pin [NTAPS * N_ACT];
__device__ int   g_pout[NTAPS * N_ACT];
__device__ int   g_cnt [NTAPS];
__device__ float g_sum[Cc], g_sq[Cc];
__device__ float g_scale[Cc], g_shift[Cc];

// ---------------- helpers ----------------------------------------------------
__device__ __forceinline__ uint32_t tf32u(float x) {
    uint32_t y;
    asm("cvt.rna.tf32.f32 %0, %1;" : "=r"(y) : "f"(x));
    return y;
}
__device__ __forceinline__ float tf32r(float x) { return __uint_as_float(tf32u(x)); }

__device__ __forceinline__ void mma8(float* d, const uint32_t* a, const uint32_t* b) {
    asm volatile(
        "mma.sync.aligned.m16n8k8.row.col.f32.tf32.tf32.f32 "
        "{%0,%1,%2,%3}, {%4,%5,%6,%7}, {%8,%9}, {%0,%1,%2,%3};"
        : "+f"(d[0]), "+f"(d[1]), "+f"(d[2]), "+f"(d[3])
        : "r"(a[0]), "r"(a[1]), "r"(a[2]), "r"(a[3]), "r"(b[0]), "r"(b[1]));
}

__device__ __forceinline__ void red_add2(float* p, float a, float b) {
    asm volatile("red.relaxed.gpu.global.add.v2.f32 [%0], {%1, %2};"
                 :: "l"(p), "f"(a), "f"(b) : "memory");
}

__device__ __forceinline__ uint32_t smem_u32(const void* p) {
    uint32_t a;
    asm("{ .reg .u64 t; cvta.to.shared.u64 t, %1; cvt.u32.u64 %0, t; }" : "=r"(a) : "l"(p));
    return a;
}

// SMEM geometry
#define WP_STRIDE 132                        // float2 units per (s,tig) row
#define WP_FLOATS (16 * 4 * WP_STRIDE * 2)   // 16896 floats
#define AS_STRIDE 36                         // floats per A row (144B)
#define AS_STAGE  (128 * AS_STRIDE)

// ---------------- utility kernels --------------------------------------------
__global__ void zero_all_k() {
    int t = threadIdx.x;
    if (t < NTAPS) g_cnt[t] = 0;
    if (t < Cc) { g_sum[t] = 0.f; g_sq[t] = 0.f; }
}

// warp-aggregated rulebook build
__global__ void rulebook_k(const int* __restrict__ nbr) {
    int i = blockIdx.x * blockDim.x + threadIdx.x;
    bool act = (i < N_ACT);
    int lane = threadIdx.x & 31;
#pragma unroll
    for (int k = 0; k < 9; k++) {
        if (k == 4) continue;
        int idx = act ? nbr[i * 9 + k] : -1;
        bool valid = idx >= 0;
        unsigned mask = __ballot_sync(0xffffffffu, valid);
        if (valid) {
            int t = (k < 4) ? k : k - 1;
            int leader = __ffs(mask) - 1;
            int base = 0;
            if (lane == leader) base = atomicAdd(&g_cnt[t], __popc(mask));
            base = __shfl_sync(mask, base, leader);
            int pos = base + __popc(mask & ((1u << lane) - 1u));
            g_pin [t * N_ACT + pos] = idx;
            g_pout[t * N_ACT + pos] = i;
        }
    }
}

// ---------------- tf32 mma.sync GEMM, cross-tile cp.async pipeline -----------
// CTA tile 128x128, K=128 in 4 chunks of 32; 8 warps (4m x 2n), 2x8 frags.
template <bool CENTER, bool BN>
__global__ void __launch_bounds__(256, 2) conv_mma_k(
    const float* __restrict__ in, const float* __restrict__ W,
    float* __restrict__ out)
{
    extern __shared__ float smem[];
    float2* Wp = (float2*)smem;                        // [16][4][WP_STRIDE]
    float*  As = smem + WP_FLOATS;                     // 2 stages x 128*36
    int*    rin  = (int*)(As + 2 * AS_STAGE);          // [2][128]
    float*  ssc  = (float*)(rin + 256);
    float*  ssh  = ssc + 128;

    const uint32_t asu = smem_u32(As);

    int tid = threadIdx.x;
    int wid = tid >> 5, lane = tid & 31;
    int wm = wid >> 1, wn = wid & 1;
    int grp = lane >> 2, tig = lane & 3;

    const float* Wk;
    const int *pin = nullptr, *pout = nullptr;
    int cnt;
    if (CENTER) {
        Wk = W;
        cnt = N_ACT;
    } else {
        int tap = blockIdx.y;
        cnt = g_cnt[tap];
        int kk = (tap < 4) ? tap : tap + 1;
        Wk = W + (long)kk * Cc * Cc;
        pin  = g_pin  + (long)tap * N_ACT;
        pout = g_pout + (long)tap * N_ACT;
    }

    // Stage W[k][n] -> paired float2 layout (tf32), once per CTA.
    for (int i = tid; i < 128 * 32; i += 256) {
        int k = i >> 5, n4 = (i & 31) * 4;
        float4 v = *(const float4*)&Wk[k * Cc + n4];
        int s = k >> 3, r = k & 7, t = r & 3, half = r >> 2;
        float* d = smem + (((s * 4 + t) * WP_STRIDE + n4) * 2 + half);
        d[0] = tf32r(v.x); d[2] = tf32r(v.y); d[4] = tf32r(v.z); d[6] = tf32r(v.w);
    }
    if (BN && tid < 128) { ssc[tid] = g_scale[tid]; ssh[tid] = g_shift[tid]; }

    int numTiles = (cnt + 127) >> 7;
    int step = gridDim.x;
    int tile0 = blockIdx.x;

    // issue one 128x32 chunk of tile into a stage via cp.async (.cg, L2 only)
    auto issue = [&](int tileI, int kc, int stage, const int* rbuf, bool valid) {
        if (valid) {
            uint32_t sbase = asu + (uint32_t)stage * (AS_STAGE * 4);
            int m0 = tileI << 7;
#pragma unroll
            for (int l = 0; l < 4; l++) {
                int idx = tid + l * 256;          // 0..1023 16B-chunks
                int rloc = idx >> 3, c16 = idx & 7;
                int rg;
                if (CENTER) { int m = m0 + rloc; rg = (m < N_ACT) ? m : -1; }
                else        rg = rbuf[rloc];
                const float* src = in + (long)(rg < 0 ? 0 : rg) * Cc + kc * 32 + c16 * 4;
                uint32_t dst = sbase + (uint32_t)(rloc * 144 + c16 * 16);
                int sz = (rg >= 0) ? 16 : 0;
                asm volatile("cp.async.cg.shared.global [%0], [%1], 16, %2;"
                             :: "r"(dst), "l"(src), "r"(sz));
            }
        }
        asm volatile("cp.async.commit_group;" ::: "memory");
    };

    // prologue: publish tile0 indices, issue its chunk 0
    if (!CENTER && tid < 128) {
        int m = (tile0 << 7) + tid;
        rin[tid] = (tile0 < numTiles && m < cnt) ? pin[m] : -1;
    }
    __syncthreads();
    issue(tile0, 0, 0, rin, tile0 < numTiles);

    int it = 0;
    for (int tile = tile0; tile < numTiles; tile += step, it++) {
        int cbuf = it & 1, nbuf = cbuf ^ 1;
        int nextTile = tile + step;
        bool nextValid = nextTile < numTiles;

        // prefetch next tile's gather indices into the other buffer
        if (!CENTER && tid < 128) {
            int m = (nextTile << 7) + tid;
            rin[nbuf * 128 + tid] = (nextValid && m < cnt) ? pin[m] : -1;
        }

        // current tile's scatter row ids -> registers (direct LDG)
        int ro[2][2];
        if (!CENTER) {
#pragma unroll
            for (int mt = 0; mt < 2; mt++) {
                int r0 = (tile << 7) + wm * 32 + mt * 16 + grp;
                ro[mt][0] = (r0     < cnt) ? pout[r0]     : -1;
                ro[mt][1] = (r0 + 8 < cnt) ? pout[r0 + 8] : -1;
            }
        }

        float acc[2][8][4];
#pragma unroll
        for (int a = 0; a < 2; a++)
#pragma unroll
            for (int b = 0; b < 8; b++)
#pragma unroll
                for (int c = 0; c < 4; c++) acc[a][b][c] = 0.f;

#pragma unroll
        for (int kc = 0; kc < 4; kc++) {
            if (kc < 3) issue(tile, kc + 1, (kc + 1) & 1, rin + cbuf * 128, true);
            else        issue(nextTile, 0, 0, rin + nbuf * 128, nextValid);

            asm volatile("cp.async.wait_group 1;" ::: "memory");
            __syncthreads();

            const float* Ast = As + (kc & 1) * AS_STAGE;

#pragma unroll
            for (int ks = 0; ks < 4; ks++) {
                int k0 = ks * 8;
                int s  = kc * 4 + ks;
                int ka = kc * 32 + k0 + tig;
                int kb = ka + 4;
                float sca = 0.f, sha = 0.f, scb = 0.f, shb = 0.f;
                if (BN) { sca = ssc[ka]; sha = ssh[ka]; scb = ssc[kb]; shb = ssh[kb]; }

                uint32_t afr[2][4], bfr[8][2];
#pragma unroll
                for (int mt = 0; mt < 2; mt++) {
                    int rb = wm * 32 + mt * 16;
                    float e0 = Ast[(rb + grp)     * AS_STRIDE + k0 + tig];
                    float e1 = Ast[(rb + grp + 8) * AS_STRIDE + k0 + tig];
                    float e2 = Ast[(rb + grp)     * AS_STRIDE + k0 + tig + 4];
                    float e3 = Ast[(rb + grp + 8) * AS_STRIDE + k0 + tig + 4];
                    if (BN) {
                        e0 = fmaxf(e0 * sca + sha, 0.f);
                        e1 = fmaxf(e1 * sca + sha, 0.f);
                        e2 = fmaxf(e2 * scb + shb, 0.f);
                        e3 = fmaxf(e3 * scb + shb, 0.f);
                    }
                    afr[mt][0] = tf32u(e0); afr[mt][1] = tf32u(e1);
                    afr[mt][2] = tf32u(e2); afr[mt][3] = tf32u(e3);
                }
                const float2* wps = Wp + (s * 4 + tig) * WP_STRIDE;
#pragma unroll
                for (int nt = 0; nt < 8; nt++) {
                    int col = wn * 64 + nt * 8 + grp;
                    float2 p = wps[col];
                    bfr[nt][0] = __float_as_uint(p.x);
                    bfr[nt][1] = __float_as_uint(p.y);
                }
#pragma unroll
                for (int mt = 0; mt < 2; mt++)
#pragma unroll
                    for (int nt = 0; nt < 8; nt++)
                        mma8(acc[mt][nt], afr[mt], bfr[nt]);
            }
            __syncthreads();
        }

        // epilogue (overlaps next tile's chunk-0 cp.async already in flight)
        int m0 = tile << 7;
#pragma unroll
        for (int mt = 0; mt < 2; mt++) {
            if (CENTER) {
                int m0r = m0 + wm * 32 + mt * 16 + grp;
                int m1r = m0r + 8;
#pragma unroll
                for (int nt = 0; nt < 8; nt++) {
                    int col = wn * 64 + nt * 8 + tig * 2;
                    if (m0r < N_ACT)
                        *(float2*)&out[(long)m0r * Cc + col] =
                            make_float2(acc[mt][nt][0], acc[mt][nt][1]);
                    if (m1r < N_ACT)
                        *(float2*)&out[(long)m1r * Cc + col] =
                            make_float2(acc[mt][nt][2], acc[mt][nt][3]);
                }
            } else {
                int ro0 = ro[mt][0], ro1 = ro[mt][1];
#pragma unroll
                for (int nt = 0; nt < 8; nt++) {
                    int col = wn * 64 + nt * 8 + tig * 2;
                    if (ro0 >= 0)
                        red_add2(&out[(long)ro0 * Cc + col], acc[mt][nt][0], acc[mt][nt][1]);
                    if (ro1 >= 0)
                        red_add2(&out[(long)ro1 * Cc + col], acc[mt][nt][2], acc[mt][nt][3]);
                }
            }
        }
    }
    asm volatile("cp.async.wait_group 0;" ::: "memory");
}

// ---------------- per-channel sum / sum-of-squares --------------------------
__global__ __launch_bounds__(256) void stats_k(const float* __restrict__ y) {
    int c4 = threadIdx.x & 31;
    int rbase = blockIdx.x * 256 + (threadIdx.x >> 5);
    float4 s = make_float4(0.f, 0.f, 0.f, 0.f);
    float4 q = make_float4(0.f, 0.f, 0.f, 0.f);
#pragma unroll 4
    for (int it = 0; it < 32; it++) {
        int r = rbase + it * 8;
        if (r < N_ACT) {
            float4 v = *(const float4*)&y[(long)r * Cc + c4 * 4];
            s.x += v.x; s.y += v.y; s.z += v.z; s.w += v.w;
            q.x += v.x * v.x; q.y += v.y * v.y; q.z += v.z * v.z; q.w += v.w * v.w;
        }
    }
    int c = c4 * 4;
    atomicAdd(&g_sum[c + 0], s.x); atomicAdd(&g_sum[c + 1], s.y);
    atomicAdd(&g_sum[c + 2], s.z); atomicAdd(&g_sum[c + 3], s.w);
    atomicAdd(&g_sq [c + 0], q.x); atomicAdd(&g_sq [c + 1], q.y);
    atomicAdd(&g_sq [c + 2], q.z); atomicAdd(&g_sq [c + 3], q.w);
}

// computes scale/shift, then re-zeros accumulators for the next use
__global__ void finalize_k(const float* __restrict__ gamma, const float* __restrict__ beta) {
    int c = threadIdx.x;
    float mean = g_sum[c] * (1.f / N_ACT);
    float var  = g_sq[c] * (1.f / N_ACT) - mean * mean;
    float istd = rsqrtf(var + EPSV);
    float sc = gamma[c] * istd;
    g_scale[c] = sc;
    g_shift[c] = beta[c] - mean * sc;
    g_sum[c] = 0.f;
    g_sq[c]  = 0.f;
}

__global__ __launch_bounds__(256) void final_k(
    const float* __restrict__ y, const float* __restrict__ x, float* __restrict__ outp)
{
    int i = blockIdx.x * blockDim.x + threadIdx.x;
    if (i >= N_ACT * Cc / 4) return;
    int c4 = (i & 31) * 4;
    float4 v  = ((const float4*)y)[i];
    float4 xv = ((const float4*)x)[i];
    float4 sc = *(const float4*)&g_scale[c4];
    float4 sh = *(const float4*)&g_shift[c4];
    float4 o;
    o.x = fmaxf(v.x * sc.x + sh.x + xv.x, 0.f);
    o.y = fmaxf(v.y * sc.y + sh.y + xv.y, 0.f);
    o.z = fmaxf(v.z * sc.z + sh.z + xv.z, 0.f);
    o.w = fmaxf(v.w * sc.w + sh.w + xv.w, 0.f);
    ((float4*)outp)[i] = o;
}

// ---------------- launch ------------------------------------------------------
extern "C" void kernel_launch(void* const* d_in, const int* in_sizes, int n_in,
                              void* d_out, int out_size)
{
    const float* x   = (const float*)d_in[0];
    const int*   nbr = (const int*)  d_in[1];
    const float* W1  = (const float*)d_in[2];
    const float* g1  = (const float*)d_in[3];
    const float* b1  = (const float*)d_in[4];
    const float* W2  = (const float*)d_in[5];
    const float* g2  = (const float*)d_in[6];
    const float* b2  = (const float*)d_in[7];
    float* out = (float*)d_out;

    float* buf1; cudaGetSymbolAddress((void**)&buf1, g_buf1);
    float* buf2; cudaGetSymbolAddress((void**)&buf2, g_buf2);

    const int SMEM = (WP_FLOATS + 2 * AS_STAGE) * 4 + 256 * 4 + 2 * 128 * 4;
    cudaFuncSetAttribute(conv_mma_k<true,  false>, cudaFuncAttributeMaxDynamicSharedMemorySize, SMEM);
    cudaFuncSetAttribute(conv_mma_k<false, false>, cudaFuncAttributeMaxDynamicSharedMemorySize, SMEM);
    cudaFuncSetAttribute(conv_mma_k<true,  true >, cudaFuncAttributeMaxDynamicSharedMemorySize, SMEM);
    cudaFuncSetAttribute(conv_mma_k<false, true >, cudaFuncAttributeMaxDynamicSharedMemorySize, SMEM);

    const int ewBlocks   = (N_ACT * Cc / 4 + 255) / 256;
    const int statBlocks = (N_ACT + 255) / 256;

    zero_all_k<<<1, 256>>>();
    rulebook_k<<<(N_ACT + 255) / 256, 256>>>(nbr);

    // ---- layer 1 (no BN on input) ----
    conv_mma_k<true,  false><<<304, 256, SMEM>>>(x, W1 + 4 * Cc * Cc, buf1);
    conv_mma_k<false, false><<<dim3(38, NTAPS), 256, SMEM>>>(x, W1, buf1);
    stats_k<<<statBlocks, 256>>>(buf1);
    finalize_k<<<1, Cc>>>(g1, b1);

    // ---- layer 2 (BN+ReLU of layer 1 fused into A loads) ----
    conv_mma_k<true,  true ><<<304, 256, SMEM>>>(buf1, W2 + 4 * Cc * Cc, buf2);
    conv_mma_k<false, true ><<<dim3(38, NTAPS), 256, SMEM>>>(buf1, W2, buf2);
    stats_k<<<statBlocks, 256>>>(buf2);
    finalize_k<<<1, Cc>>>(g2, b2);
    final_k<<<ewBlocks, 256>>>(buf2, x, out);
}

// round 8
// speedup vs baseline: 4.1165x; 2.2274x over previous
#include <cuda_runtime.h>
#include <cstdint>

#define N_ACT 300000
#define Cc 128
#define NTAPS 8
#define EPSV 1e-4f

// ---------------- scratch (device globals) ----------------------------------
__device__ float g_buf1[N_ACT * Cc];
__device__ float g_buf2[N_ACT * Cc];
__device__ int   g_pin [NTAPS * N_ACT];
__device__ int   g_pout[NTAPS * N_ACT];
__device__ int   g_cnt [NTAPS];
__device__ float g_sum[Cc], g_sq[Cc];
__device__ float g_scale[Cc], g_shift[Cc];

// ---------------- helpers ----------------------------------------------------
__device__ __forceinline__ uint32_t tf32u(float x) {
    uint32_t y;
    asm("cvt.rna.tf32.f32 %0, %1;" : "=r"(y) : "f"(x));
    return y;
}
__device__ __forceinline__ float tf32r(float x) { return __uint_as_float(tf32u(x)); }

__device__ __forceinline__ void mma8(float* d, const uint32_t* a, const uint32_t* b) {
    asm volatile(
        "mma.sync.aligned.m16n8k8.row.col.f32.tf32.tf32.f32 "
        "{%0,%1,%2,%3}, {%4,%5,%6,%7}, {%8,%9}, {%0,%1,%2,%3};"
        : "+f"(d[0]), "+f"(d[1]), "+f"(d[2]), "+f"(d[3])
        : "r"(a[0]), "r"(a[1]), "r"(a[2]), "r"(a[3]), "r"(b[0]), "r"(b[1]));
}

__device__ __forceinline__ void red_add2(float* p, float a, float b) {
    asm volatile("red.relaxed.gpu.global.add.v2.f32 [%0], {%1, %2};"
                 :: "l"(p), "f"(a), "f"(b) : "memory");
}

__device__ __forceinline__ uint32_t smem_u32(const void* p) {
    uint32_t a;
    asm("{ .reg .u64 t; cvta.to.shared.u64 t, %1; cvt.u32.u64 %0, t; }" : "=r"(a) : "l"(p));
    return a;
}

// SMEM geometry
#define WP_STRIDE 132                        // float2 units per (s,tig) row
#define WP_FLOATS (16 * 4 * WP_STRIDE * 2)   // 16896 floats
#define AS_STRIDE 36                         // floats per A row (144B)
#define AS_STAGE  (128 * AS_STRIDE)

// ---------------- utility kernels --------------------------------------------
__global__ void zero_all_k() {
    int t = threadIdx.x;
    if (t < NTAPS) g_cnt[t] = 0;
    if (t < Cc) { g_sum[t] = 0.f; g_sq[t] = 0.f; }
}

// block-aggregated rulebook build: smem counters, 8 global atomics per block
__global__ __launch_bounds__(256) void rulebook_k(const int* __restrict__ nbr) {
    __shared__ int scnt[NTAPS], sbase[NTAPS];
    int tid = threadIdx.x;
    if (tid < NTAPS) scnt[tid] = 0;
    __syncthreads();

    int i = blockIdx.x * 256 + tid;
    bool act = (i < N_ACT);
    int idxv[NTAPS], lpos[NTAPS];
#pragma unroll
    for (int k = 0; k < 9; k++) {
        if (k == 4) continue;
        int t = (k < 4) ? k : k - 1;
        int idx = act ? nbr[i * 9 + k] : -1;
        idxv[t] = idx;
        lpos[t] = (idx >= 0) ? atomicAdd(&scnt[t], 1) : -1;
    }
    __syncthreads();
    if (tid < NTAPS) sbase[tid] = atomicAdd(&g_cnt[tid], scnt[tid]);
    __syncthreads();
#pragma unroll
    for (int t = 0; t < NTAPS; t++) {
        if (lpos[t] >= 0) {
            int pos = sbase[t] + lpos[t];
            g_pin [t * N_ACT + pos] = idxv[t];
            g_pout[t * N_ACT + pos] = i;
        }
    }
}

// ---------------- tf32 mma.sync GEMM, cross-tile cp.async pipeline -----------
// CTA tile 128x128, K=128 in 4 chunks of 32; 8 warps (4m x 2n), 2x8 frags.
template <bool CENTER, bool BN>
__global__ void __launch_bounds__(256, 2) conv_mma_k(
    const float* __restrict__ in, const float* __restrict__ W,
    float* __restrict__ out)
{
    extern __shared__ float smem[];
    float2* Wp = (float2*)smem;                        // [16][4][WP_STRIDE]
    float*  As = smem + WP_FLOATS;                     // 2 stages x 128*36
    int*    rin  = (int*)(As + 2 * AS_STAGE);          // [2][128]
    float*  ssc  = (float*)(rin + 256);
    float*  ssh  = ssc + 128;

    const uint32_t asu = smem_u32(As);

    int tid = threadIdx.x;
    int wid = tid >> 5, lane = tid & 31;
    int wm = wid >> 1, wn = wid & 1;
    int grp = lane >> 2, tig = lane & 3;

    const float* Wk;
    const int *pin = nullptr, *pout = nullptr;
    int cnt;
    if (CENTER) {
        Wk = W;
        cnt = N_ACT;
    } else {
        int tap = blockIdx.y;
        cnt = g_cnt[tap];
        int kk = (tap < 4) ? tap : tap + 1;
        Wk = W + (long)kk * Cc * Cc;
        pin  = g_pin  + (long)tap * N_ACT;
        pout = g_pout + (long)tap * N_ACT;
    }

    // Stage W[k][n] -> paired float2 layout (tf32), once per CTA.
    for (int i = tid; i < 128 * 32; i += 256) {
        int k = i >> 5, n4 = (i & 31) * 4;
        float4 v = *(const float4*)&Wk[k * Cc + n4];
        int s = k >> 3, r = k & 7, t = r & 3, half = r >> 2;
        float* d = smem + (((s * 4 + t) * WP_STRIDE + n4) * 2 + half);
        d[0] = tf32r(v.x); d[2] = tf32r(v.y); d[4] = tf32r(v.z); d[6] = tf32r(v.w);
    }
    if (BN && tid < 128) { ssc[tid] = g_scale[tid]; ssh[tid] = g_shift[tid]; }

    int numTiles = (cnt + 127) >> 7;
    int step = gridDim.x;
    int tile0 = blockIdx.x;

    auto issue = [&](int tileI, int kc, int stage, const int* rbuf, bool valid) {
        if (valid) {
            uint32_t sbase = asu + (uint32_t)stage * (AS_STAGE * 4);
            int m0 = tileI << 7;
#pragma unroll
            for (int l = 0; l < 4; l++) {
                int idx = tid + l * 256;          // 0..1023 16B-chunks
                int rloc = idx >> 3, c16 = idx & 7;
                int rg;
                if (CENTER) { int m = m0 + rloc; rg = (m < N_ACT) ? m : -1; }
                else        rg = rbuf[rloc];
                const float* src = in + (long)(rg < 0 ? 0 : rg) * Cc + kc * 32 + c16 * 4;
                uint32_t dst = sbase + (uint32_t)(rloc * 144 + c16 * 16);
                int sz = (rg >= 0) ? 16 : 0;
                asm volatile("cp.async.cg.shared.global [%0], [%1], 16, %2;"
                             :: "r"(dst), "l"(src), "r"(sz));
            }
        }
        asm volatile("cp.async.commit_group;" ::: "memory");
    };

    if (!CENTER && tid < 128) {
        int m = (tile0 << 7) + tid;
        rin[tid] = (tile0 < numTiles && m < cnt) ? pin[m] : -1;
    }
    __syncthreads();
    issue(tile0, 0, 0, rin, tile0 < numTiles);

    int it = 0;
    for (int tile = tile0; tile < numTiles; tile += step, it++) {
        int cbuf = it & 1, nbuf = cbuf ^ 1;
        int nextTile = tile + step;
        bool nextValid = nextTile < numTiles;

        if (!CENTER && tid < 128) {
            int m = (nextTile << 7) + tid;
            rin[nbuf * 128 + tid] = (nextValid && m < cnt) ? pin[m] : -1;
        }

        int ro[2][2];
        if (!CENTER) {
#pragma unroll
            for (int mt = 0; mt < 2; mt++) {
                int r0 = (tile << 7) + wm * 32 + mt * 16 + grp;
                ro[mt][0] = (r0     < cnt) ? pout[r0]     : -1;
                ro[mt][1] = (r0 + 8 < cnt) ? pout[r0 + 8] : -1;
            }
        }

        float acc[2][8][4];
#pragma unroll
        for (int a = 0; a < 2; a++)
#pragma unroll
            for (int b = 0; b < 8; b++)
#pragma unroll
                for (int c = 0; c < 4; c++) acc[a][b][c] = 0.f;

#pragma unroll
        for (int kc = 0; kc < 4; kc++) {
            if (kc < 3) issue(tile, kc + 1, (kc + 1) & 1, rin + cbuf * 128, true);
            else        issue(nextTile, 0, 0, rin + nbuf * 128, nextValid);

            asm volatile("cp.async.wait_group 1;" ::: "memory");
            __syncthreads();

            const float* Ast = As + (kc & 1) * AS_STAGE;

#pragma unroll
            for (int ks = 0; ks < 4; ks++) {
                int k0 = ks * 8;
                int s  = kc * 4 + ks;
                int ka = kc * 32 + k0 + tig;
                int kb = ka + 4;
                float sca = 0.f, sha = 0.f, scb = 0.f, shb = 0.f;
                if (BN) { sca = ssc[ka]; sha = ssh[ka]; scb = ssc[kb]; shb = ssh[kb]; }

                uint32_t afr[2][4], bfr[8][2];
#pragma unroll
                for (int mt = 0; mt < 2; mt++) {
                    int rb = wm * 32 + mt * 16;
                    float e0 = Ast[(rb + grp)     * AS_STRIDE + k0 + tig];
                    float e1 = Ast[(rb + grp + 8) * AS_STRIDE + k0 + tig];
                    float e2 = Ast[(rb + grp)     * AS_STRIDE + k0 + tig + 4];
                    float e3 = Ast[(rb + grp + 8) * AS_STRIDE + k0 + tig + 4];
                    if (BN) {
                        e0 = fmaxf(e0 * sca + sha, 0.f);
                        e1 = fmaxf(e1 * sca + sha, 0.f);
                        e2 = fmaxf(e2 * scb + shb, 0.f);
                        e3 = fmaxf(e3 * scb + shb, 0.f);
                    }
                    afr[mt][0] = tf32u(e0); afr[mt][1] = tf32u(e1);
                    afr[mt][2] = tf32u(e2); afr[mt][3] = tf32u(e3);
                }
                const float2* wps = Wp + (s * 4 + tig) * WP_STRIDE;
#pragma unroll
                for (int nt = 0; nt < 8; nt++) {
                    int col = wn * 64 + nt * 8 + grp;
                    float2 p = wps[col];
                    bfr[nt][0] = __float_as_uint(p.x);
                    bfr[nt][1] = __float_as_uint(p.y);
                }
#pragma unroll
                for (int mt = 0; mt < 2; mt++)
#pragma unroll
                    for (int nt = 0; nt < 8; nt++)
                        mma8(acc[mt][nt], afr[mt], bfr[nt]);
            }
            __syncthreads();
        }

        int m0 = tile << 7;
#pragma unroll
        for (int mt = 0; mt < 2; mt++) {
            if (CENTER) {
                int m0r = m0 + wm * 32 + mt * 16 + grp;
                int m1r = m0r + 8;
#pragma unroll
                for (int nt = 0; nt < 8; nt++) {
                    int col = wn * 64 + nt * 8 + tig * 2;
                    if (m0r < N_ACT)
                        *(float2*)&out[(long)m0r * Cc + col] =
                            make_float2(acc[mt][nt][0], acc[mt][nt][1]);
                    if (m1r < N_ACT)
                        *(float2*)&out[(long)m1r * Cc + col] =
                            make_float2(acc[mt][nt][2], acc[mt][nt][3]);
                }
            } else {
                int ro0 = ro[mt][0], ro1 = ro[mt][1];
#pragma unroll
                for (int nt = 0; nt < 8; nt++) {
                    int col = wn * 64 + nt * 8 + tig * 2;
                    if (ro0 >= 0)
                        red_add2(&out[(long)ro0 * Cc + col], acc[mt][nt][0], acc[mt][nt][1]);
                    if (ro1 >= 0)
                        red_add2(&out[(long)ro1 * Cc + col], acc[mt][nt][2], acc[mt][nt][3]);
                }
            }
        }
    }
    asm volatile("cp.async.wait_group 0;" ::: "memory");
}

// ---------------- per-channel stats: two-level reduction ---------------------
// grid-stride over rows; smem reduce across the 8 warps; 256 atomics per block.
__global__ __launch_bounds__(256) void stats_k(const float* __restrict__ y) {
    __shared__ float ssum[8][32][4];
    __shared__ float ssq [8][32][4];

    int tid = threadIdx.x;
    int wid = tid >> 5;
    int c4  = tid & 31;

    float4 s = make_float4(0.f, 0.f, 0.f, 0.f);
    float4 q = make_float4(0.f, 0.f, 0.f, 0.f);
    for (int r = blockIdx.x * 8 + wid; r < N_ACT; r += gridDim.x * 8) {
        float4 v = *(const float4*)&y[(long)r * Cc + c4 * 4];
        s.x += v.x; s.y += v.y; s.z += v.z; s.w += v.w;
        q.x += v.x * v.x; q.y += v.y * v.y; q.z += v.z * v.z; q.w += v.w * v.w;
    }
    ssum[wid][c4][0] = s.x; ssum[wid][c4][1] = s.y;
    ssum[wid][c4][2] = s.z; ssum[wid][c4][3] = s.w;
    ssq [wid][c4][0] = q.x; ssq [wid][c4][1] = q.y;
    ssq [wid][c4][2] = q.z; ssq [wid][c4][3] = q.w;
    __syncthreads();

    if (tid < 128) {
        int cg = tid >> 2, j = tid & 3;
        float ts = 0.f, tq = 0.f;
#pragma unroll
        for (int w = 0; w < 8; w++) { ts += ssum[w][cg][j]; tq += ssq[w][cg][j]; }
        atomicAdd(&g_sum[tid], ts);
        atomicAdd(&g_sq [tid], tq);
    }
}

// computes scale/shift, then re-zeros accumulators for the next use
__global__ void finalize_k(const float* __restrict__ gamma, const float* __restrict__ beta) {
    int c = threadIdx.x;
    float mean = g_sum[c] * (1.f / N_ACT);
    float var  = g_sq[c] * (1.f / N_ACT) - mean * mean;
    float istd = rsqrtf(var + EPSV);
    float sc = gamma[c] * istd;
    g_scale[c] = sc;
    g_shift[c] = beta[c] - mean * sc;
    g_sum[c] = 0.f;
    g_sq[c]  = 0.f;
}

__global__ __launch_bounds__(256) void final_k(
    const float* __restrict__ y, const float* __restrict__ x, float* __restrict__ outp)
{
    int i = blockIdx.x * blockDim.x + threadIdx.x;
    if (i >= N_ACT * Cc / 4) return;
    int c4 = (i & 31) * 4;
    float4 v  = ((const float4*)y)[i];
    float4 xv = ((const float4*)x)[i];
    float4 sc = *(const float4*)&g_scale[c4];
    float4 sh = *(const float4*)&g_shift[c4];
    float4 o;
    o.x = fmaxf(v.x * sc.x + sh.x + xv.x, 0.f);
    o.y = fmaxf(v.y * sc.y + sh.y + xv.y, 0.f);
    o.z = fmaxf(v.z * sc.z + sh.z + xv.z, 0.f);
    o.w = fmaxf(v.w * sc.w + sh.w + xv.w, 0.f);
    ((float4*)outp)[i] = o;
}

// ---------------- launch ------------------------------------------------------
extern "C" void kernel_launch(void* const* d_in, const int* in_sizes, int n_in,
                              void* d_out, int out_size)
{
    const float* x   = (const float*)d_in[0];
    const int*   nbr = (const int*)  d_in[1];
    const float* W1  = (const float*)d_in[2];
    const float* g1  = (const float*)d_in[3];
    const float* b1  = (const float*)d_in[4];
    const float* W2  = (const float*)d_in[5];
    const float* g2  = (const float*)d_in[6];
    const float* b2  = (const float*)d_in[7];
    float* out = (float*)d_out;

    float* buf1; cudaGetSymbolAddress((void**)&buf1, g_buf1);
    float* buf2; cudaGetSymbolAddress((void**)&buf2, g_buf2);

    const int SMEM = (WP_FLOATS + 2 * AS_STAGE) * 4 + 256 * 4 + 2 * 128 * 4;
    cudaFuncSetAttribute(conv_mma_k<true,  false>, cudaFuncAttributeMaxDynamicSharedMemorySize, SMEM);
    cudaFuncSetAttribute(conv_mma_k<false, false>, cudaFuncAttributeMaxDynamicSharedMemorySize, SMEM);
    cudaFuncSetAttribute(conv_mma_k<true,  true >, cudaFuncAttributeMaxDynamicSharedMemorySize, SMEM);
    cudaFuncSetAttribute(conv_mma_k<false, true >, cudaFuncAttributeMaxDynamicSharedMemorySize, SMEM);

    const int ewBlocks = (N_ACT * Cc / 4 + 255) / 256;

    zero_all_k<<<1, 256>>>();
    rulebook_k<<<(N_ACT + 255) / 256, 256>>>(nbr);

    // ---- layer 1 (no BN on input) ----
    conv_mma_k<true,  false><<<304, 256, SMEM>>>(x, W1 + 4 * Cc * Cc, buf1);
    conv_mma_k<false, false><<<dim3(38, NTAPS), 256, SMEM>>>(x, W1, buf1);
    stats_k<<<304, 256>>>(buf1);
    finalize_k<<<1, Cc>>>(g1, b1);

    // ---- layer 2 (BN+ReLU of layer 1 fused into A loads) ----
    conv_mma_k<true,  true ><<<304, 256, SMEM>>>(buf1, W2 + 4 * Cc * Cc, buf2);
    conv_mma_k<false, true ><<<dim3(38, NTAPS), 256, SMEM>>>(buf1, W2, buf2);
    stats_k<<<304, 256>>>(buf2);
    finalize_k<<<1, Cc>>>(g2, b2);
    final_k<<<ewBlocks, 256>>>(buf2, x, out);
}